// round 8
// baseline (speedup 1.0000x reference)
#include <cuda_runtime.h>
#include <cuda_bf16.h>
#include <math.h>

// Problem constants (fixed by the dataset)
#define NODES 100000
#define EDGES 3200000
#define F     256        // in/hidden feature width (also GEMM K)
#define F4    (F/4)      // float4 width
#define CLS   40         // classes

// ---------------- scratch (static device globals; no allocation) -------------
__device__ float g_bufA[(size_t)NODES * F];   // ping
__device__ float g_bufB[(size_t)NODES * F];   // pong
__device__ int   g_cnt[NODES];                // counts, then reused as fill cursor
__device__ int   g_rowptr[NODES + 1];
__device__ int   g_srcs[EDGES];
__device__ float g_vals[EDGES];
__device__ int   g_is64;                      // edge_index dtype flag

// ---------------- packed f32x2 helpers (sm_103a FFMA2 path) -------------------
#define FFMA2(c, a, b) \
    asm volatile("fma.rn.f32x2 %0, %1, %2, %0;" : "+l"(c) : "l"(a), "l"(b))
#define PACK2(d, x) \
    asm volatile("mov.b64 %0, {%1, %1};" : "=l"(d) : "r"(x))
#define UNPACK2(lo, hi, d) \
    asm volatile("mov.b64 {%0, %1}, %2;" : "=r"(lo), "=r"(hi) : "l"(d))

// ---------------- init: zero counters + detect edge dtype (fused) ------------
__global__ void init_kernel(const void* ei) {
    int i = blockIdx.x * blockDim.x + threadIdx.x;
    if (i < NODES) g_cnt[i] = 0;
    if (blockIdx.x == 0 && threadIdx.x == 0) {
        // int64 edge_index read as int64 gives values in [0,NODES) for all 64
        // probes iff the tensor really is int64 (an int32 pair reinterpreted
        // as int64 has a huge high word with overwhelming probability).
        const long long* p = (const long long*)ei;
        int ok = 1;
        #pragma unroll 1
        for (int j = 0; j < 64; j++) {
            long long v = p[j];
            if (v < 0 || v >= NODES) { ok = 0; break; }
        }
        g_is64 = ok;
    }
}

__device__ __forceinline__ int load_idx(const void* ei, int half, int e, int is64) {
    if (is64) return (int)((const long long*)ei)[(size_t)half * EDGES + e];
    return ((const int*)ei)[(size_t)half * EDGES + e];
}

// ---------------- CSR build ---------------------------------------------------
__global__ void count_kernel(const void* __restrict__ ei) {
    int e = blockIdx.x * blockDim.x + threadIdx.x;
    if (e < EDGES) {
        int d = load_idx(ei, 1, e, g_is64);
        atomicAdd(&g_cnt[d], 1);
    }
}

// single-block exclusive scan of g_cnt -> g_rowptr (n = NODES).
// Also zeroes g_cnt in the write-back pass so scatter can reuse it as the
// per-row fill cursor (scan is the last reader of the counts).
__global__ __launch_bounds__(1024) void scan_kernel() {
    __shared__ int s[1024];
    const int n = NODES;
    int tid = threadIdx.x;
    int chunk = (n + 1023) >> 10;
    int start = min(tid * chunk, n);
    int end   = min(start + chunk, n);
    int sum = 0;
    for (int i = start; i < end; i++) sum += g_cnt[i];
    s[tid] = sum;
    __syncthreads();
    for (int off = 1; off < 1024; off <<= 1) {
        int t = 0;
        if (tid >= off) t = s[tid - off];
        __syncthreads();
        s[tid] += t;
        __syncthreads();
    }
    int run = s[tid] - sum;   // exclusive prefix for this chunk
    for (int i = start; i < end; i++) {
        int c = g_cnt[i];
        g_rowptr[i] = run;
        g_cnt[i] = 0;         // reset -> fill cursor for scatter
        run += c;
    }
    if (tid == 0) g_rowptr[n] = s[1023];
}

__global__ void scatter_kernel(const void* __restrict__ ei,
                               const float* __restrict__ ev) {
    int e = blockIdx.x * blockDim.x + threadIdx.x;
    if (e < EDGES) {
        int is64 = g_is64;
        int d = load_idx(ei, 1, e, is64);
        int s = load_idx(ei, 0, e, is64);
        int p = atomicAdd(&g_cnt[d], 1);
        int idx = g_rowptr[d] + p;
        g_srcs[idx] = s;
        g_vals[idx] = ev[e];
    }
}

// ---------------- SPMM (gather side, CSR by dst, zero atomics) ----------------
// width 256: one block of 64 threads per dst row, each thread owns one float4 col
__global__ __launch_bounds__(64) void spmm256_kernel(const float* __restrict__ g,
                                                     float* __restrict__ h,
                                                     int dorelu) {
    int row = blockIdx.x;
    int tid = threadIdx.x;
    int beg = g_rowptr[row];
    int end = g_rowptr[row + 1];
    __shared__ int   s_src[64];
    __shared__ float s_val[64];
    const float4* gp = (const float4*)g;
    float4 acc = make_float4(0.f, 0.f, 0.f, 0.f);
    for (int base = beg; base < end; base += 64) {
        int n = min(64, end - base);
        if (tid < n) { s_src[tid] = g_srcs[base + tid]; s_val[tid] = g_vals[base + tid]; }
        __syncthreads();
        #pragma unroll 4
        for (int i = 0; i < n; i++) {
            float  w = s_val[i];
            float4 v = gp[(size_t)s_src[i] * F4 + tid];
            acc.x += w * v.x; acc.y += w * v.y; acc.z += w * v.z; acc.w += w * v.w;
        }
        if (base + 64 < end) __syncthreads();   // skip trailing barrier on last batch
    }
    if (dorelu) {
        acc.x = fmaxf(acc.x, 0.f); acc.y = fmaxf(acc.y, 0.f);
        acc.z = fmaxf(acc.z, 0.f); acc.w = fmaxf(acc.w, 0.f);
    }
    ((float4*)h)[(size_t)row * F4 + tid] = acc;
}

// width 40 + fused log_softmax: one block of 64 threads per dst row.
// tids 0..39 own one class column; warp 0 then reduces max/logsumexp from smem
// and tids 0..39 write (acc - lse) to out with a streaming (evict-first) store
// so the write-once output doesn't displace the L2-resident feature table.
__global__ __launch_bounds__(64) void spmm40_lsm_kernel(const float* __restrict__ g,
                                                        float* __restrict__ out) {
    int row = blockIdx.x;
    int tid = threadIdx.x;
    int beg = g_rowptr[row];
    int end = g_rowptr[row + 1];
    __shared__ int   s_src[64];
    __shared__ float s_val[64];
    __shared__ float s_cls[CLS];
    __shared__ float s_lse;
    float acc = 0.f;
    for (int base = beg; base < end; base += 64) {
        int n = min(64, end - base);
        if (tid < n) { s_src[tid] = g_srcs[base + tid]; s_val[tid] = g_vals[base + tid]; }
        __syncthreads();
        if (tid < CLS) {
            #pragma unroll 4
            for (int i = 0; i < n; i++)
                acc += s_val[i] * g[(size_t)s_src[i] * CLS + tid];
        }
        if (base + 64 < end) __syncthreads();
    }
    if (tid < CLS) s_cls[tid] = acc;
    __syncthreads();
    if (tid < 32) {
        float v0 = s_cls[tid];
        float v1 = (tid < CLS - 32) ? s_cls[32 + tid] : -INFINITY;
        float m = fmaxf(v0, v1);
        #pragma unroll
        for (int o = 16; o; o >>= 1) m = fmaxf(m, __shfl_xor_sync(0xffffffffu, m, o));
        float s = expf(v0 - m) + ((tid < CLS - 32) ? expf(v1 - m) : 0.f);
        #pragma unroll
        for (int o = 16; o; o >>= 1) s += __shfl_xor_sync(0xffffffffu, s, o);
        if (tid == 0) s_lse = logf(s) + m;
    }
    __syncthreads();
    if (tid < CLS) __stcs(&out[(size_t)row * CLS + tid], acc - s_lse);
}

// ---------------- tiled fp32 GEMM: FFMA2 + double-buffered smem ---------------
// C[M,N] = A[M,GK] @ B[GK,N], GK = 256 compile-time (all call sites use F).
// 128x64 block tile, 256 threads, 8x4 microtile per thread as 4 row-PAIRS x
// 4 cols of fma.rn.f32x2 (2 FMA/lane/inst).
// Two-stage smem pipeline: while computing on buf[t&1], tile t+1 is prefetched
// from gmem into registers, then stored to buf[(t+1)&1]; one barrier per
// iteration (the barrier at end of iter t-1 orders the last reads of
// buf[(t+1)&1] before iter t overwrites it).
#define BM 128
#define BN 64
#define BK 32
#define GK F            // compile-time K: full unroll of the pipeline loop
#define GT (GK / BK)    // 8 tiles
__global__ __launch_bounds__(256) void gemm_kernel(const float* __restrict__ A,
                                                   const float* __restrict__ B,
                                                   float* __restrict__ C,
                                                   int M, int N) {
    __shared__ float As[2][BK * BM];   // As[buf][k*BM + m] (transposed, m contiguous)
    __shared__ float Bs[2][BK * BN];   // Bs[buf][k*BN + n]
    int tid = threadIdx.x;
    int m0 = blockIdx.y * BM;
    int n0 = blockIdx.x * BN;
    int tx = tid & 15;           // col group (4 cols)
    int ty = tid >> 4;           // row group (8 rows = 4 row-pairs)
    int arow = tid >> 3;         // 0..31 (A-load row within pass)
    int akq  = (tid & 7) * 4;    // A-load k offset (float4)

    unsigned long long acc2[4][4];   // [row-pair][col], each = packed (f32,f32)
    #pragma unroll
    for (int i = 0; i < 4; i++)
        #pragma unroll
        for (int j = 0; j < 4; j++) acc2[i][j] = 0ull;

    float4 pa[4];                    // A prefetch regs (4 rows x float4)
    float  pb[8];                    // B prefetch regs (8 elements)

    // ---- prefetch helpers (inlined lambdas keep the loads register-resident)
    auto load_tile = [&](int kk) {
        #pragma unroll
        for (int p = 0; p < 4; p++) {
            int gr = m0 + p * 32 + arow;
            pa[p] = (gr < M)
                ? *(const float4*)(A + (size_t)gr * GK + kk + akq)
                : make_float4(0.f, 0.f, 0.f, 0.f);
        }
        #pragma unroll
        for (int l = 0; l < 8; l++) {
            int li = l * 256 + tid;
            int bk = li >> 6;
            int bn = li & 63;
            int gc = n0 + bn;
            pb[l] = (gc < N) ? B[(size_t)(kk + bk) * N + gc] : 0.f;
        }
    };
    auto store_tile = [&](int buf) {
        #pragma unroll
        for (int p = 0; p < 4; p++) {
            int r = p * 32 + arow;
            As[buf][(akq + 0) * BM + r] = pa[p].x;
            As[buf][(akq + 1) * BM + r] = pa[p].y;
            As[buf][(akq + 2) * BM + r] = pa[p].z;
            As[buf][(akq + 3) * BM + r] = pa[p].w;
        }
        #pragma unroll
        for (int l = 0; l < 8; l++) {
            int li = l * 256 + tid;
            Bs[buf][(li >> 6) * BN + (li & 63)] = pb[l];
        }
    };

    // prologue: tile 0 into buf 0
    load_tile(0);
    store_tile(0);
    __syncthreads();

    #pragma unroll
    for (int t = 0; t < GT; t++) {
        int cur = t & 1;
        if (t + 1 < GT) load_tile((t + 1) * BK);   // overlap with compute below
        #pragma unroll
        for (int k = 0; k < BK; k++) {
            // A fragment: 8 rows = 4 packed pairs, loaded as two 16B LDS
            const ulonglong2* ap =
                (const ulonglong2*)&As[cur][k * BM + ty * 8];
            ulonglong2 alo = ap[0];     // pairs (r0,r1) (r2,r3)
            ulonglong2 ahi = ap[1];     // pairs (r4,r5) (r6,r7)
            // B fragment: 4 cols, broadcast-packed
            float4 b4 = *(const float4*)&Bs[cur][k * BN + tx * 4];
            unsigned long long bb0, bb1, bb2, bb3;
            PACK2(bb0, __float_as_uint(b4.x));
            PACK2(bb1, __float_as_uint(b4.y));
            PACK2(bb2, __float_as_uint(b4.z));
            PACK2(bb3, __float_as_uint(b4.w));
            FFMA2(acc2[0][0], alo.x, bb0);
            FFMA2(acc2[0][1], alo.x, bb1);
            FFMA2(acc2[0][2], alo.x, bb2);
            FFMA2(acc2[0][3], alo.x, bb3);
            FFMA2(acc2[1][0], alo.y, bb0);
            FFMA2(acc2[1][1], alo.y, bb1);
            FFMA2(acc2[1][2], alo.y, bb2);
            FFMA2(acc2[1][3], alo.y, bb3);
            FFMA2(acc2[2][0], ahi.x, bb0);
            FFMA2(acc2[2][1], ahi.x, bb1);
            FFMA2(acc2[2][2], ahi.x, bb2);
            FFMA2(acc2[2][3], ahi.x, bb3);
            FFMA2(acc2[3][0], ahi.y, bb0);
            FFMA2(acc2[3][1], ahi.y, bb1);
            FFMA2(acc2[3][2], ahi.y, bb2);
            FFMA2(acc2[3][3], ahi.y, bb3);
        }
        if (t + 1 < GT) {
            store_tile(cur ^ 1);    // other buffer; prior-iter barrier ordered
            __syncthreads();        // its last readers ahead of this store
        }
    }

    // epilogue: unpack row-pairs and store with M/N guards
    #pragma unroll
    for (int p = 0; p < 4; p++) {
        int r0 = m0 + ty * 8 + 2 * p;
        int r1 = r0 + 1;
        #pragma unroll
        for (int j = 0; j < 4; j++) {
            int c = n0 + tx * 4 + j;
            if (c >= N) continue;
            unsigned int lo, hi;
            UNPACK2(lo, hi, acc2[p][j]);
            if (r0 < M) C[(size_t)r0 * N + c] = __uint_as_float(lo);
            if (r1 < M) C[(size_t)r1 * N + c] = __uint_as_float(hi);
        }
    }
}

// ---------------- launch ------------------------------------------------------
extern "C" void kernel_launch(void* const* d_in, const int* in_sizes, int n_in,
                              void* d_out, int out_size) {
    const float* x  = (const float*)d_in[0];
    const void*  ei = d_in[1];                 // int64 or int32 (detected on device)
    const float* ev = (const float*)d_in[2];
    const float* W1 = (const float*)d_in[3];
    const float* W2 = (const float*)d_in[4];
    const float* W3 = (const float*)d_in[5];
    float* out = (float*)d_out;

    float *bufA, *bufB;
    cudaGetSymbolAddress((void**)&bufA, g_bufA);
    cudaGetSymbolAddress((void**)&bufB, g_bufB);

    const int M = NODES;
    dim3 gemm_grid_wide((F + BN - 1) / BN, (M + BM - 1) / BM);   // 4 x 782
    dim3 gemm_grid_cls((CLS + BN - 1) / BN, (M + BM - 1) / BM);  // 1 x 782
    int eblocks = (EDGES + 255) / 256;
    int nblocks = (NODES + 255) / 256;

    // CSR build (deterministic work per launch, fully graph-capturable)
    init_kernel<<<nblocks, 256>>>(ei);
    count_kernel<<<eblocks, 256>>>(ei);
    scan_kernel<<<1, 1024>>>();
    scatter_kernel<<<eblocks, 256>>>(ei, ev);

    // layer 1:  h1 = relu(spmm(x @ W1))        [commuted: (Ax)W = A(xW)]
    gemm_kernel<<<gemm_grid_wide, 256>>>(x, W1, bufA, M, F);
    spmm256_kernel<<<NODES, 64>>>(bufA, bufB, /*relu=*/1);

    // layer 2:  h2 = relu(spmm(h1 @ W2))
    gemm_kernel<<<gemm_grid_wide, 256>>>(bufB, W2, bufA, M, F);
    spmm256_kernel<<<NODES, 64>>>(bufA, bufB, /*relu=*/1);

    // layer 3:  out = log_softmax(spmm(h2 @ W3))   (width-40 spmm + fused lsm)
    gemm_kernel<<<gemm_grid_cls, 256>>>(bufB, W3, bufA, M, CLS);
    spmm40_lsm_kernel<<<NODES, 64>>>(bufA, out);
}